// round 1
// baseline (speedup 1.0000x reference)
#include <cuda_runtime.h>

#define BATCH 4
#define SEQ   2048
#define NH    16
#define DH    64
#define DM    1024
#define MROWS (BATCH*SEQ)   // 8192

// Scratch (static device globals; no runtime allocation)
__device__ float g_q[(size_t)BATCH*NH*SEQ*DH];
__device__ float g_k[(size_t)BATCH*NH*SEQ*DH];
__device__ float g_v[(size_t)BATCH*NH*SEQ*DH];
__device__ float g_o[(size_t)MROWS*DM];

// ---------------------------------------------------------------------------
// QKV projection: per (m-tile, head, {Q,K,V}) compute a 128x64 tile of
// out[b,h,p,d] = sum_m x[b,p,m] * W[h,m,d] + bias[h,d]
// ---------------------------------------------------------------------------
__global__ __launch_bounds__(256) void qkv_kernel(
    const float* __restrict__ X,
    const float* __restrict__ Qw, const float* __restrict__ Qb,
    const float* __restrict__ Kw, const float* __restrict__ Kb,
    const float* __restrict__ Vw, const float* __restrict__ Vb)
{
    const int m0    = blockIdx.x * 128;
    const int h     = blockIdx.y;
    const int which = blockIdx.z;

    const float* W    = (which == 0 ? Qw : which == 1 ? Kw : Vw) + (size_t)h * DM * DH;
    const float* bias = (which == 0 ? Qb : which == 1 ? Kb : Vb) + h * DH;
    float* Out        = (which == 0 ? g_q : which == 1 ? g_k : g_v);

    __shared__ float As[16][128];  // As[k][m]
    __shared__ float Bs[16][64];   // Bs[k][n]

    const int tid   = threadIdx.x;
    const int tr    = tid >> 4;        // 0..15
    const int tc    = tid & 15;        // 0..15
    const int mbase = tr * 8;
    const int nbase = tc * 4;

    float acc[8][4];
#pragma unroll
    for (int i = 0; i < 8; i++)
#pragma unroll
        for (int j = 0; j < 4; j++) acc[i][j] = 0.f;

    const int ar  = tid >> 2;   // 0..63  row within 64-row chunk (A loads)
    const int ac4 = tid & 3;    // float4 col (of 4) within 16 cols
    const int br  = tid >> 4;   // 0..15  row (B loads)
    const int bc4 = tid & 15;   // float4 col within 64

    for (int k0 = 0; k0 < DM; k0 += 16) {
#pragma unroll
        for (int hh = 0; hh < 2; hh++) {
            int row = ar + hh * 64;
            float4 va = *(const float4*)&X[(size_t)(m0 + row) * DM + k0 + ac4 * 4];
            As[ac4 * 4 + 0][row] = va.x;
            As[ac4 * 4 + 1][row] = va.y;
            As[ac4 * 4 + 2][row] = va.z;
            As[ac4 * 4 + 3][row] = va.w;
        }
        *(float4*)&Bs[br][bc4 * 4] =
            *(const float4*)&W[(size_t)(k0 + br) * DH + bc4 * 4];
        __syncthreads();

#pragma unroll
        for (int kk = 0; kk < 16; kk++) {
            float a[8], bb[4];
            *(float4*)&a[0] = *(const float4*)&As[kk][mbase];
            *(float4*)&a[4] = *(const float4*)&As[kk][mbase + 4];
            *(float4*)&bb[0] = *(const float4*)&Bs[kk][nbase];
#pragma unroll
            for (int i = 0; i < 8; i++)
#pragma unroll
                for (int j = 0; j < 4; j++) acc[i][j] += a[i] * bb[j];
        }
        __syncthreads();
    }

#pragma unroll
    for (int i = 0; i < 8; i++) {
        int m = m0 + mbase + i;
        int b = m / SEQ, p = m % SEQ;
        float4 r;
        r.x = acc[i][0] + bias[nbase + 0];
        r.y = acc[i][1] + bias[nbase + 1];
        r.z = acc[i][2] + bias[nbase + 2];
        r.w = acc[i][3] + bias[nbase + 3];
        *(float4*)&Out[(((size_t)(b * NH + h)) * SEQ + p) * DH + nbase] = r;
    }
}

// ---------------------------------------------------------------------------
// Causal flash attention: grid (16 q-tiles of 128, B*H). 256 threads.
// Thread pair (2*r, 2*r+1) owns q-row r of the tile; each thread owns 32
// S-columns and 32 output d-columns (half = tid&1).
// ---------------------------------------------------------------------------
__global__ __launch_bounds__(256) void attn_kernel()
{
    const int qt = blockIdx.x;
    const int bh = blockIdx.y;
    const int q0 = qt * 128;
    const int b  = bh / NH, h = bh % NH;

    const float* qp = g_q + (size_t)bh * SEQ * DH;
    const float* kp = g_k + (size_t)bh * SEQ * DH;
    const float* vp = g_v + (size_t)bh * SEQ * DH;

    __shared__ float Ks[64][64];
    __shared__ float Vs[64][64];

    const int tid   = threadIdx.x;
    const int r     = tid >> 1;
    const int half  = tid & 1;
    const int dbase = half * 32;   // both this thread's S-col base and d-col base
    const int qg    = q0 + r;

    float qreg[64];
#pragma unroll
    for (int d4 = 0; d4 < 16; d4++)
        *(float4*)&qreg[d4 * 4] = *(const float4*)&qp[(size_t)qg * DH + d4 * 4];

    float acc[32];
#pragma unroll
    for (int i = 0; i < 32; i++) acc[i] = 0.f;
    float mrow = -1e30f, lsum = 0.f;

    const int nkt = (q0 + 127) / 64 + 1;
    for (int kt = 0; kt < nkt; kt++) {
        const int k0 = kt * 64;
        __syncthreads();
#pragma unroll
        for (int i = 0; i < 4; i++) {
            int idx = tid + i * 256;       // float4 index 0..1023
            int row = idx >> 4;
            int c4  = idx & 15;
            *(float4*)&Ks[row][c4 * 4] =
                *(const float4*)&kp[(size_t)(k0 + row) * DH + c4 * 4];
            *(float4*)&Vs[row][c4 * 4] =
                *(const float4*)&vp[(size_t)(k0 + row) * DH + c4 * 4];
        }
        __syncthreads();

        // S = (Q K^T) * 1/sqrt(64) for my 32 columns
        float p[32];
        const bool need_mask = (k0 + 63 > q0);
#pragma unroll
        for (int j = 0; j < 32; j++) {
            const int jj = dbase + j;
            float sum = 0.f;
#pragma unroll
            for (int d4 = 0; d4 < 16; d4++) {
                float4 kv = *(const float4*)&Ks[jj][d4 * 4];
                sum += qreg[d4 * 4 + 0] * kv.x;
                sum += qreg[d4 * 4 + 1] * kv.y;
                sum += qreg[d4 * 4 + 2] * kv.z;
                sum += qreg[d4 * 4 + 3] * kv.w;
            }
            p[j] = sum * 0.125f;
        }
        if (need_mask) {
#pragma unroll
            for (int j = 0; j < 32; j++)
                if (k0 + dbase + j > qg) p[j] = -1e30f;
        }

        // online softmax (pair-wide reduction via shuffle)
        float mloc = p[0];
#pragma unroll
        for (int j = 1; j < 32; j++) mloc = fmaxf(mloc, p[j]);
        mloc = fmaxf(mloc, __shfl_xor_sync(0xffffffffu, mloc, 1));
        const float mnew = fmaxf(mrow, mloc);
        float ls = 0.f;
#pragma unroll
        for (int j = 0; j < 32; j++) {
            p[j] = __expf(p[j] - mnew);
            ls += p[j];
        }
        ls += __shfl_xor_sync(0xffffffffu, ls, 1);
        const float scale = __expf(mrow - mnew);
        lsum = lsum * scale + ls;
        mrow = mnew;
#pragma unroll
        for (int i = 0; i < 32; i++) acc[i] *= scale;

        // O += P * V : first my own 32 S-cols, then partner's via shuffle
        const int jb_self  = dbase;
        const int jb_other = 32 - dbase;
#pragma unroll
        for (int j = 0; j < 32; j++) {
            const float pj = p[j];
            const int vr = jb_self + j;
#pragma unroll
            for (int d4 = 0; d4 < 8; d4++) {
                float4 vv = *(const float4*)&Vs[vr][dbase + d4 * 4];
                acc[d4 * 4 + 0] += pj * vv.x;
                acc[d4 * 4 + 1] += pj * vv.y;
                acc[d4 * 4 + 2] += pj * vv.z;
                acc[d4 * 4 + 3] += pj * vv.w;
            }
        }
#pragma unroll
        for (int j = 0; j < 32; j++) {
            const float pj = __shfl_xor_sync(0xffffffffu, p[j], 1);
            const int vr = jb_other + j;
#pragma unroll
            for (int d4 = 0; d4 < 8; d4++) {
                float4 vv = *(const float4*)&Vs[vr][dbase + d4 * 4];
                acc[d4 * 4 + 0] += pj * vv.x;
                acc[d4 * 4 + 1] += pj * vv.y;
                acc[d4 * 4 + 2] += pj * vv.z;
                acc[d4 * 4 + 3] += pj * vv.w;
            }
        }
    }

    const float inv = 1.f / lsum;
    float* op = &g_o[((size_t)(b * SEQ) + qg) * DM + h * DH + dbase];
#pragma unroll
    for (int d4 = 0; d4 < 8; d4++) {
        float4 rr;
        rr.x = acc[d4 * 4 + 0] * inv;
        rr.y = acc[d4 * 4 + 1] * inv;
        rr.z = acc[d4 * 4 + 2] * inv;
        rr.w = acc[d4 * 4 + 3] * inv;
        *(float4*)&op[d4 * 4] = rr;
    }
}

// ---------------------------------------------------------------------------
// Output projection: out[m, n] = sum_k g_o[m, k] * O_w[k, n] + O_b[n]
// O_w (h,d,m-layout) flattens to a row-major [1024,1024] matrix.
// ---------------------------------------------------------------------------
__global__ __launch_bounds__(256) void oproj_kernel(
    const float* __restrict__ Ow, const float* __restrict__ Ob,
    float* __restrict__ out)
{
    const int m0 = blockIdx.x * 128;
    const int n0 = blockIdx.y * 64;

    __shared__ float As[16][128];
    __shared__ float Bs[16][64];

    const int tid   = threadIdx.x;
    const int tr    = tid >> 4;
    const int tc    = tid & 15;
    const int mbase = tr * 8;
    const int nbase = tc * 4;

    float acc[8][4];
#pragma unroll
    for (int i = 0; i < 8; i++)
#pragma unroll
        for (int j = 0; j < 4; j++) acc[i][j] = 0.f;

    const int ar  = tid >> 2;
    const int ac4 = tid & 3;
    const int br  = tid >> 4;
    const int bc4 = tid & 15;

    for (int k0 = 0; k0 < DM; k0 += 16) {
#pragma unroll
        for (int hh = 0; hh < 2; hh++) {
            int row = ar + hh * 64;
            float4 va = *(const float4*)&g_o[(size_t)(m0 + row) * DM + k0 + ac4 * 4];
            As[ac4 * 4 + 0][row] = va.x;
            As[ac4 * 4 + 1][row] = va.y;
            As[ac4 * 4 + 2][row] = va.z;
            As[ac4 * 4 + 3][row] = va.w;
        }
        *(float4*)&Bs[br][bc4 * 4] =
            *(const float4*)&Ow[(size_t)(k0 + br) * DM + n0 + bc4 * 4];
        __syncthreads();

#pragma unroll
        for (int kk = 0; kk < 16; kk++) {
            float a[8], bb[4];
            *(float4*)&a[0] = *(const float4*)&As[kk][mbase];
            *(float4*)&a[4] = *(const float4*)&As[kk][mbase + 4];
            *(float4*)&bb[0] = *(const float4*)&Bs[kk][nbase];
#pragma unroll
            for (int i = 0; i < 8; i++)
#pragma unroll
                for (int j = 0; j < 4; j++) acc[i][j] += a[i] * bb[j];
        }
        __syncthreads();
    }

#pragma unroll
    for (int i = 0; i < 8; i++) {
        int m = m0 + mbase + i;
        float4 rr;
        rr.x = acc[i][0] + Ob[n0 + nbase + 0];
        rr.y = acc[i][1] + Ob[n0 + nbase + 1];
        rr.z = acc[i][2] + Ob[n0 + nbase + 2];
        rr.w = acc[i][3] + Ob[n0 + nbase + 3];
        *(float4*)&out[(size_t)m * DM + n0 + nbase] = rr;
    }
}

extern "C" void kernel_launch(void* const* d_in, const int* in_sizes, int n_in,
                              void* d_out, int out_size)
{
    const float* x  = (const float*)d_in[0];
    const float* Qw = (const float*)d_in[1];
    const float* Qb = (const float*)d_in[2];
    const float* Kw = (const float*)d_in[3];
    const float* Kb = (const float*)d_in[4];
    const float* Vw = (const float*)d_in[5];
    const float* Vb = (const float*)d_in[6];
    const float* Ow = (const float*)d_in[7];
    const float* Ob = (const float*)d_in[8];
    float* out = (float*)d_out;

    qkv_kernel<<<dim3(MROWS / 128, NH, 3), 256>>>(x, Qw, Qb, Kw, Kb, Vw, Vb);
    attn_kernel<<<dim3(SEQ / 128, BATCH * NH), 256>>>();
    oproj_kernel<<<dim3(MROWS / 128, DM / 64), 256>>>(Ow, Ob, out);
}

// round 2
// speedup vs baseline: 3.7791x; 3.7791x over previous
#include <cuda_runtime.h>
#include <cstdint>

#define BATCH 4
#define SEQ   2048
#define NH    16
#define DH    64
#define DM    1024
#define MROWS (BATCH*SEQ)   // 8192

// Scratch (static device globals; no runtime allocation)
__device__ float g_q[(size_t)BATCH*NH*SEQ*DH];
__device__ float g_k[(size_t)BATCH*NH*SEQ*DH];
__device__ float g_v[(size_t)BATCH*NH*SEQ*DH];
__device__ float g_o[(size_t)MROWS*DM];

__device__ __forceinline__ uint32_t f2tf(float x) {
    uint32_t u;
    asm("cvt.rna.tf32.f32 %0, %1;" : "=r"(u) : "f"(x));
    return u;
}
__device__ __forceinline__ float f2tff(float x) { return __uint_as_float(f2tf(x)); }

__device__ __forceinline__ void mma_tf32(float* c,
    uint32_t a0, uint32_t a1, uint32_t a2, uint32_t a3,
    uint32_t b0, uint32_t b1)
{
    asm volatile(
        "mma.sync.aligned.m16n8k8.row.col.f32.tf32.tf32.f32 "
        "{%0,%1,%2,%3}, {%4,%5,%6,%7}, {%8,%9}, {%0,%1,%2,%3};"
        : "+f"(c[0]), "+f"(c[1]), "+f"(c[2]), "+f"(c[3])
        : "r"(a0), "r"(a1), "r"(a2), "r"(a3), "r"(b0), "r"(b1));
}

// ---------------------------------------------------------------------------
// QKV projection: tf32 tensor-core GEMM, 128x64 tile per block.
// out[b,h,p,d] = sum_m x[b,p,m] * W[h,m,d] + bias[h,d]
// ---------------------------------------------------------------------------
__global__ __launch_bounds__(256) void qkv_kernel(
    const float* __restrict__ X,
    const float* __restrict__ Qw, const float* __restrict__ Qb,
    const float* __restrict__ Kw, const float* __restrict__ Kb,
    const float* __restrict__ Vw, const float* __restrict__ Vb)
{
    const int m0    = blockIdx.x * 128;
    const int h     = blockIdx.y;
    const int which = blockIdx.z;

    const float* W    = (which == 0 ? Qw : which == 1 ? Kw : Vw) + (size_t)h * DM * DH;
    const float* bias = (which == 0 ? Qb : which == 1 ? Kb : Vb) + h * DH;
    float* Out        = (which == 0 ? g_q : which == 1 ? g_k : g_v);

    __shared__ float As[128][36];   // [m][k], BK=32, pad->banks (4g+t) distinct
    __shared__ float Bs[32][72];    // [k][n], pad->banks (8t+g) distinct

    const int tid  = threadIdx.x;
    const int lane = tid & 31;
    const int w    = tid >> 5;
    const int wm   = w >> 1;     // 0..3
    const int wn   = w & 1;      // 0..1
    const int g    = lane >> 2;  // 0..7
    const int t    = lane & 3;   // 0..3

    float c[2][4][4];
#pragma unroll
    for (int mt = 0; mt < 2; mt++)
#pragma unroll
        for (int nt = 0; nt < 4; nt++)
#pragma unroll
            for (int i = 0; i < 4; i++) c[mt][nt][i] = 0.f;

    for (int k0 = 0; k0 < DM; k0 += 32) {
#pragma unroll
        for (int i = 0; i < 4; i++) {
            int lin = tid + i * 256;       // float4 id, 1024 total
            int row = lin >> 3;
            int c4  = lin & 7;
            float4 v = *(const float4*)&X[(size_t)(m0 + row) * DM + k0 + c4 * 4];
            As[row][c4 * 4 + 0] = f2tff(v.x);
            As[row][c4 * 4 + 1] = f2tff(v.y);
            As[row][c4 * 4 + 2] = f2tff(v.z);
            As[row][c4 * 4 + 3] = f2tff(v.w);
        }
#pragma unroll
        for (int i = 0; i < 2; i++) {
            int lin = tid + i * 256;       // 512 float4 total
            int row = lin >> 4;
            int c4  = lin & 15;
            float4 v = *(const float4*)&W[(size_t)(k0 + row) * DH + c4 * 4];
            Bs[row][c4 * 4 + 0] = f2tff(v.x);
            Bs[row][c4 * 4 + 1] = f2tff(v.y);
            Bs[row][c4 * 4 + 2] = f2tff(v.z);
            Bs[row][c4 * 4 + 3] = f2tff(v.w);
        }
        __syncthreads();

#pragma unroll
        for (int ks = 0; ks < 4; ks++) {
            uint32_t a[2][4], bb[4][2];
#pragma unroll
            for (int mt = 0; mt < 2; mt++) {
                int r0 = wm * 32 + mt * 16 + g;
                a[mt][0] = __float_as_uint(As[r0][ks * 8 + t]);
                a[mt][1] = __float_as_uint(As[r0 + 8][ks * 8 + t]);
                a[mt][2] = __float_as_uint(As[r0][ks * 8 + t + 4]);
                a[mt][3] = __float_as_uint(As[r0 + 8][ks * 8 + t + 4]);
            }
#pragma unroll
            for (int nt = 0; nt < 4; nt++) {
                int col = wn * 32 + nt * 8 + g;
                bb[nt][0] = __float_as_uint(Bs[ks * 8 + t][col]);
                bb[nt][1] = __float_as_uint(Bs[ks * 8 + t + 4][col]);
            }
#pragma unroll
            for (int mt = 0; mt < 2; mt++)
#pragma unroll
                for (int nt = 0; nt < 4; nt++)
                    mma_tf32(c[mt][nt], a[mt][0], a[mt][1], a[mt][2], a[mt][3],
                             bb[nt][0], bb[nt][1]);
        }
        __syncthreads();
    }

#pragma unroll
    for (int mt = 0; mt < 2; mt++) {
        int m = m0 + wm * 32 + mt * 16 + g;
        int b_ = m >> 11, p = m & 2047;
        size_t base = ((size_t)(b_ * NH + h)) * SEQ;
#pragma unroll
        for (int nt = 0; nt < 4; nt++) {
            int col = wn * 32 + nt * 8 + 2 * t;
            float bx = bias[col], by = bias[col + 1];
            float2 v0 = { c[mt][nt][0] + bx, c[mt][nt][1] + by };
            float2 v1 = { c[mt][nt][2] + bx, c[mt][nt][3] + by };
            *(float2*)&Out[(base + p) * DH + col]     = v0;
            *(float2*)&Out[(base + p + 8) * DH + col] = v1;
        }
    }
}

// ---------------------------------------------------------------------------
// Causal flash attention with tf32 mma. Block = 128 q-rows, 8 warps (16 rows
// each). K/V tiles of 64 s-positions staged in smem. Q fragments in registers
// with 1/sqrt(64) folded in. P transposed C->A layout via quad shuffles.
// ---------------------------------------------------------------------------
__global__ __launch_bounds__(256) void attn_kernel()
{
    const int qt = blockIdx.x;
    const int bh = blockIdx.y;
    const int q0 = qt * 128;
    const int b  = bh / NH, h = bh % NH;

    const float* qp = g_q + (size_t)bh * SEQ * DH;
    const float* kp = g_k + (size_t)bh * SEQ * DH;
    const float* vp = g_v + (size_t)bh * SEQ * DH;

    __shared__ float Ks[64][68];   // [s][d] : b0=Ks[8nt+g][8kt+t] -> banks 4g+t
    __shared__ float Vs[64][72];   // [s][d] : b0=Vs[8kt+t][8nt+g] -> banks 8t+g

    const int tid  = threadIdx.x;
    const int lane = tid & 31;
    const int w    = tid >> 5;   // warp 0..7, rows w*16..w*16+15
    const int g    = lane >> 2;
    const int t    = lane & 3;

    // Preload Q fragments (scaled)
    uint32_t qa[8][4];
    {
        const float* qr0 = qp + (size_t)(q0 + w * 16 + g) * DH;
        const float* qr1 = qr0 + 8 * DH;
#pragma unroll
        for (int kt = 0; kt < 8; kt++) {
            qa[kt][0] = f2tf(qr0[kt * 8 + t] * 0.125f);
            qa[kt][1] = f2tf(qr1[kt * 8 + t] * 0.125f);
            qa[kt][2] = f2tf(qr0[kt * 8 + t + 4] * 0.125f);
            qa[kt][3] = f2tf(qr1[kt * 8 + t + 4] * 0.125f);
        }
    }

    float o[8][4];
#pragma unroll
    for (int nt = 0; nt < 8; nt++)
#pragma unroll
        for (int i = 0; i < 4; i++) o[nt][i] = 0.f;
    float m0r = -1e30f, m1r = -1e30f, l0 = 0.f, l1 = 0.f;

    const int row0 = q0 + w * 16 + g;
    const int row1 = row0 + 8;

    const int nkt = q0 / 64 + 2;
    for (int kt2 = 0; kt2 < nkt; kt2++) {
        const int k0 = kt2 * 64;
        __syncthreads();
#pragma unroll
        for (int i = 0; i < 4; i++) {
            int lin = tid + i * 256;
            int row = lin >> 4;
            int c4  = lin & 15;
            float4 kv = *(const float4*)&kp[(size_t)(k0 + row) * DH + c4 * 4];
            Ks[row][c4 * 4 + 0] = f2tff(kv.x);
            Ks[row][c4 * 4 + 1] = f2tff(kv.y);
            Ks[row][c4 * 4 + 2] = f2tff(kv.z);
            Ks[row][c4 * 4 + 3] = f2tff(kv.w);
            float4 vv = *(const float4*)&vp[(size_t)(k0 + row) * DH + c4 * 4];
            Vs[row][c4 * 4 + 0] = f2tff(vv.x);
            Vs[row][c4 * 4 + 1] = f2tff(vv.y);
            Vs[row][c4 * 4 + 2] = f2tff(vv.z);
            Vs[row][c4 * 4 + 3] = f2tff(vv.w);
        }
        __syncthreads();

        // S = (Q/8) @ K^T  — fragments s[nt] cover s-cols k0+nt*8..+7
        float s[8][4];
#pragma unroll
        for (int nt = 0; nt < 8; nt++) {
            s[nt][0] = s[nt][1] = s[nt][2] = s[nt][3] = 0.f;
        }
#pragma unroll
        for (int kt = 0; kt < 8; kt++) {
#pragma unroll
            for (int nt = 0; nt < 8; nt++) {
                uint32_t b0 = __float_as_uint(Ks[nt * 8 + g][kt * 8 + t]);
                uint32_t b1 = __float_as_uint(Ks[nt * 8 + g][kt * 8 + t + 4]);
                mma_tf32(s[nt], qa[kt][0], qa[kt][1], qa[kt][2], qa[kt][3], b0, b1);
            }
        }

        // causal mask (only near diagonal)
        if (k0 + 63 > q0) {
#pragma unroll
            for (int nt = 0; nt < 8; nt++) {
                int col = k0 + nt * 8 + 2 * t;
                if (col > row0)     s[nt][0] = -1e30f;
                if (col + 1 > row0) s[nt][1] = -1e30f;
                if (col > row1)     s[nt][2] = -1e30f;
                if (col + 1 > row1) s[nt][3] = -1e30f;
            }
        }

        // online softmax (rows row0, row1; 4 lanes per row)
        float mx0 = -1e30f, mx1 = -1e30f;
#pragma unroll
        for (int nt = 0; nt < 8; nt++) {
            mx0 = fmaxf(mx0, fmaxf(s[nt][0], s[nt][1]));
            mx1 = fmaxf(mx1, fmaxf(s[nt][2], s[nt][3]));
        }
        mx0 = fmaxf(mx0, __shfl_xor_sync(0xffffffffu, mx0, 1));
        mx0 = fmaxf(mx0, __shfl_xor_sync(0xffffffffu, mx0, 2));
        mx1 = fmaxf(mx1, __shfl_xor_sync(0xffffffffu, mx1, 1));
        mx1 = fmaxf(mx1, __shfl_xor_sync(0xffffffffu, mx1, 2));

        const float m0n = fmaxf(m0r, mx0);
        const float m1n = fmaxf(m1r, mx1);
        const float sc0 = __expf(m0r - m0n);
        const float sc1 = __expf(m1r - m1n);
        m0r = m0n; m1r = m1n;

        float r0 = 0.f, r1 = 0.f;
#pragma unroll
        for (int nt = 0; nt < 8; nt++) {
            s[nt][0] = __expf(s[nt][0] - m0n);
            s[nt][1] = __expf(s[nt][1] - m0n);
            s[nt][2] = __expf(s[nt][2] - m1n);
            s[nt][3] = __expf(s[nt][3] - m1n);
            r0 += s[nt][0] + s[nt][1];
            r1 += s[nt][2] + s[nt][3];
        }
        r0 += __shfl_xor_sync(0xffffffffu, r0, 1);
        r0 += __shfl_xor_sync(0xffffffffu, r0, 2);
        r1 += __shfl_xor_sync(0xffffffffu, r1, 1);
        r1 += __shfl_xor_sync(0xffffffffu, r1, 2);
        l0 = l0 * sc0 + r0;
        l1 = l1 * sc1 + r1;

#pragma unroll
        for (int nt = 0; nt < 8; nt++) {
            o[nt][0] *= sc0; o[nt][1] *= sc0;
            o[nt][2] *= sc1; o[nt][3] *= sc1;
        }

        // O += P @ V. Transpose P (C layout -> A layout) via quad shuffles.
        const int s0l = (lane & ~3) | (t >> 1);
        const int s1l = s0l + 2;
        const bool e  = (t & 1);
#pragma unroll
        for (int kt = 0; kt < 8; kt++) {
            float v00 = __shfl_sync(0xffffffffu, s[kt][0], s0l);
            float v01 = __shfl_sync(0xffffffffu, s[kt][1], s0l);
            float v10 = __shfl_sync(0xffffffffu, s[kt][2], s0l);
            float v11 = __shfl_sync(0xffffffffu, s[kt][3], s0l);
            float w00 = __shfl_sync(0xffffffffu, s[kt][0], s1l);
            float w01 = __shfl_sync(0xffffffffu, s[kt][1], s1l);
            float w10 = __shfl_sync(0xffffffffu, s[kt][2], s1l);
            float w11 = __shfl_sync(0xffffffffu, s[kt][3], s1l);
            uint32_t pa0 = f2tf(e ? v01 : v00);
            uint32_t pa1 = f2tf(e ? v11 : v10);
            uint32_t pa2 = f2tf(e ? w01 : w00);
            uint32_t pa3 = f2tf(e ? w11 : w10);
#pragma unroll
            for (int nt = 0; nt < 8; nt++) {
                uint32_t b0 = __float_as_uint(Vs[kt * 8 + t][nt * 8 + g]);
                uint32_t b1 = __float_as_uint(Vs[kt * 8 + t + 4][nt * 8 + g]);
                mma_tf32(o[nt], pa0, pa1, pa2, pa3, b0, b1);
            }
        }
    }

    const float inv0 = 1.f / l0;
    const float inv1 = 1.f / l1;
    float* or0 = g_o + ((size_t)(b * SEQ) + row0) * DM + h * DH;
    float* or1 = or0 + (size_t)8 * DM;
#pragma unroll
    for (int nt = 0; nt < 8; nt++) {
        int col = nt * 8 + 2 * t;
        float2 v0 = { o[nt][0] * inv0, o[nt][1] * inv0 };
        float2 v1 = { o[nt][2] * inv1, o[nt][3] * inv1 };
        *(float2*)&or0[col] = v0;
        *(float2*)&or1[col] = v1;
    }
}

// ---------------------------------------------------------------------------
// Output projection: tf32 GEMM, out[m,n] = sum_k g_o[m,k]*Ow[k,n] + Ob[n]
// ---------------------------------------------------------------------------
__global__ __launch_bounds__(256) void oproj_kernel(
    const float* __restrict__ Ow, const float* __restrict__ Ob,
    float* __restrict__ out)
{
    const int m0 = blockIdx.x * 128;
    const int n0 = blockIdx.y * 64;

    __shared__ float As[128][36];
    __shared__ float Bs[32][72];

    const int tid  = threadIdx.x;
    const int lane = tid & 31;
    const int w    = tid >> 5;
    const int wm   = w >> 1;
    const int wn   = w & 1;
    const int g    = lane >> 2;
    const int t    = lane & 3;

    float c[2][4][4];
#pragma unroll
    for (int mt = 0; mt < 2; mt++)
#pragma unroll
        for (int nt = 0; nt < 4; nt++)
#pragma unroll
            for (int i = 0; i < 4; i++) c[mt][nt][i] = 0.f;

    for (int k0 = 0; k0 < DM; k0 += 32) {
#pragma unroll
        for (int i = 0; i < 4; i++) {
            int lin = tid + i * 256;
            int row = lin >> 3;
            int c4  = lin & 7;
            float4 v = *(const float4*)&g_o[(size_t)(m0 + row) * DM + k0 + c4 * 4];
            As[row][c4 * 4 + 0] = f2tff(v.x);
            As[row][c4 * 4 + 1] = f2tff(v.y);
            As[row][c4 * 4 + 2] = f2tff(v.z);
            As[row][c4 * 4 + 3] = f2tff(v.w);
        }
#pragma unroll
        for (int i = 0; i < 2; i++) {
            int lin = tid + i * 256;
            int row = lin >> 4;
            int c4  = lin & 15;
            float4 v = *(const float4*)&Ow[(size_t)(k0 + row) * DM + n0 + c4 * 4];
            Bs[row][c4 * 4 + 0] = f2tff(v.x);
            Bs[row][c4 * 4 + 1] = f2tff(v.y);
            Bs[row][c4 * 4 + 2] = f2tff(v.z);
            Bs[row][c4 * 4 + 3] = f2tff(v.w);
        }
        __syncthreads();

#pragma unroll
        for (int ks = 0; ks < 4; ks++) {
            uint32_t a[2][4], bb[4][2];
#pragma unroll
            for (int mt = 0; mt < 2; mt++) {
                int r0 = wm * 32 + mt * 16 + g;
                a[mt][0] = __float_as_uint(As[r0][ks * 8 + t]);
                a[mt][1] = __float_as_uint(As[r0 + 8][ks * 8 + t]);
                a[mt][2] = __float_as_uint(As[r0][ks * 8 + t + 4]);
                a[mt][3] = __float_as_uint(As[r0 + 8][ks * 8 + t + 4]);
            }
#pragma unroll
            for (int nt = 0; nt < 4; nt++) {
                int col = wn * 32 + nt * 8 + g;
                bb[nt][0] = __float_as_uint(Bs[ks * 8 + t][col]);
                bb[nt][1] = __float_as_uint(Bs[ks * 8 + t + 4][col]);
            }
#pragma unroll
            for (int mt = 0; mt < 2; mt++)
#pragma unroll
                for (int nt = 0; nt < 4; nt++)
                    mma_tf32(c[mt][nt], a[mt][0], a[mt][1], a[mt][2], a[mt][3],
                             bb[nt][0], bb[nt][1]);
        }
        __syncthreads();
    }

#pragma unroll
    for (int mt = 0; mt < 2; mt++) {
        int m = m0 + wm * 32 + mt * 16 + g;
#pragma unroll
        for (int nt = 0; nt < 4; nt++) {
            int col = n0 + wn * 32 + nt * 8 + 2 * t;
            float bx = Ob[col], by = Ob[col + 1];
            float2 v0 = { c[mt][nt][0] + bx, c[mt][nt][1] + by };
            float2 v1 = { c[mt][nt][2] + bx, c[mt][nt][3] + by };
            *(float2*)&out[(size_t)m * DM + col]       = v0;
            *(float2*)&out[(size_t)(m + 8) * DM + col] = v1;
        }
    }
}

extern "C" void kernel_launch(void* const* d_in, const int* in_sizes, int n_in,
                              void* d_out, int out_size)
{
    const float* x  = (const float*)d_in[0];
    const float* Qw = (const float*)d_in[1];
    const float* Qb = (const float*)d_in[2];
    const float* Kw = (const float*)d_in[3];
    const float* Kb = (const float*)d_in[4];
    const float* Vw = (const float*)d_in[5];
    const float* Vb = (const float*)d_in[6];
    const float* Ow = (const float*)d_in[7];
    const float* Ob = (const float*)d_in[8];
    float* out = (float*)d_out;

    qkv_kernel<<<dim3(MROWS / 128, NH, 3), 256>>>(x, Qw, Qb, Kw, Kb, Vw, Vb);
    attn_kernel<<<dim3(SEQ / 128, BATCH * NH), 256>>>();
    oproj_kernel<<<dim3(MROWS / 128, DM / 64), 256>>>(Ow, Ob, out);
}